// round 2
// baseline (speedup 1.0000x reference)
#include <cuda_runtime.h>
#include <math.h>

#define B_ 256
#define T_ 1024
#define V_ 96
#define H_ 128

typedef unsigned long long ull;

// Device-global scratch (allocation-free per harness rules)
__device__ __align__(16) float g_proj[V_ * H_];      // emb @ W_ih0^T + b_ih0 + b_hh0
__device__ __align__(16) float g_y0[B_ * T_ * H_];   // layer-0 outputs
__device__ __align__(16) float g_y1[B_ * T_ * H_];   // layer-1 outputs
__device__ __align__(16) float g_fcWt[64 * 96 * 2];  // fc_W transposed as [kp][v] float2 pairs

// packed fp32x2 FMA (Blackwell FFMA2)
__device__ __forceinline__ ull ffma2(ull a, ull b, ull c) {
    ull d;
    asm("fma.rn.f32x2 %0, %1, %2, %3;" : "=l"(d) : "l"(a), "l"(b), "l"(c));
    return d;
}
__device__ __forceinline__ float hadd(ull a) {
    float x, y;
    asm("mov.b64 {%0, %1}, %2;" : "=f"(x), "=f"(y) : "l"(a));
    return x + y;
}

// ---------------------------------------------------------------------------
// Projected embedding table: g_proj[v][j] = sum_h emb[v][h]*W_ih0[j][h] + b
// ---------------------------------------------------------------------------
__global__ void k_proj(const float* __restrict__ emb, const float* __restrict__ Wih0,
                       const float* __restrict__ bih0, const float* __restrict__ bhh0) {
    __shared__ float er[H_];
    int v = blockIdx.x, j = threadIdx.x;
    er[j] = emb[v * H_ + j];
    __syncthreads();
    float s = bih0[j] + bhh0[j];
    const float* wr = Wih0 + j * H_;
#pragma unroll 8
    for (int h = 0; h < H_; h++) s += er[h] * wr[h];
    g_proj[v * H_ + j] = s;
}

// Transpose fc_W into pair-major [kp][v] layout for k_fc
__global__ void k_wt(const float* __restrict__ fcW) {
    int idx = blockIdx.x * 256 + threadIdx.x;   // 6144 = 96*64
    if (idx >= 96 * 64) return;
    int v = idx >> 6, kp = idx & 63;
    ((float2*)g_fcWt)[kp * 96 + v] = ((const float2*)fcW)[v * 64 + kp];
}

// ---------------------------------------------------------------------------
// Layer-0 recurrence. 128 CTAs x 256 threads, 2 batch/CTA.
// Thread (j = tid>>1, kh = tid&1): k-half split inside lane pair, shfl.bfly
// reduction, double-buffered h -> ONE barrier per step.
// ---------------------------------------------------------------------------
__global__ void __launch_bounds__(256, 1)
k_l0(const int* __restrict__ x, const float* __restrict__ Whh0, float* __restrict__ hid0) {
    extern __shared__ float sm[];
    float* proj_s = sm;                    // 12288 floats (48KB)
    float* h0s    = sm + 12288;            // [2][256]
    int*   x_s    = (int*)(sm + 12288 + 512);  // [2][1024]

    int tid = threadIdx.x;
    int j = tid >> 1, kh = tid & 1;
    int b0 = blockIdx.x * 2;

    ull w0p[32];
    const ull* Wp = (const ull*)Whh0;
    int wbase = j * 64 + kh * 32;          // pair idx: cols [kh*64, kh*64+64)
#pragma unroll
    for (int i = 0; i < 32; i++) w0p[i] = Wp[wbase + i];

    for (int i = tid; i < (V_ * H_) / 4; i += 256)
        ((float4*)proj_s)[i] = ((const float4*)g_proj)[i];
    for (int i = tid; i < 2 * T_; i += 256) {
        int b = i >> 10, tt = i & 1023;
        x_s[i] = x[(b0 + b) * T_ + tt];
        (void)b; (void)tt;
    }
    h0s[tid] = 0.0f;                       // buffer 0 = h at t=0
    __syncthreads();

    for (int t = 0; t < T_; t++) {
        const ulonglong2* h2 = (const ulonglong2*)(h0s + (t & 1) * 256);
        int hb = kh * 16;
        ull a0 = 0, a0b = 0, a1 = 0, a1b = 0;
#pragma unroll
        for (int i = 0; i < 16; i++) {
            ulonglong2 hv0 = h2[hb + i];
            ulonglong2 hv1 = h2[32 + hb + i];
            a0  = ffma2(w0p[2 * i],     hv0.x, a0);
            a0b = ffma2(w0p[2 * i + 1], hv0.y, a0b);
            a1  = ffma2(w0p[2 * i],     hv1.x, a1);
            a1b = ffma2(w0p[2 * i + 1], hv1.y, a1b);
        }
        float p0 = hadd(a0) + hadd(a0b);
        float p1 = hadd(a1) + hadd(a1b);
        p0 += __shfl_xor_sync(0xffffffffu, p0, 1);
        p1 += __shfl_xor_sync(0xffffffffu, p1, 1);

        float v = kh ? p1 : p0;            // lane kh owns batch b0+kh
        int xi = x_s[kh * T_ + t];
        float nh = tanhf(v + proj_s[xi * H_ + j]);
        h0s[((t + 1) & 1) * 256 + kh * 128 + j] = nh;
        g_y0[((size_t)(b0 + kh) * T_ + t) * H_ + j] = nh;
        if (t == T_ - 1) hid0[(b0 + kh) * H_ + j] = nh;
        __syncthreads();
    }
}

// ---------------------------------------------------------------------------
// Layer-1 recurrence with fused input projection. Same structure, 2 matvecs.
// y0 double-buffered via register prefetch.
// ---------------------------------------------------------------------------
__global__ void __launch_bounds__(256, 1)
k_l1(const float* __restrict__ Wih1, const float* __restrict__ Whh1,
     const float* __restrict__ bih1, const float* __restrict__ bhh1,
     float* __restrict__ hid1) {
    __shared__ float bias_s[128];
    __shared__ __align__(16) float h1s[2][256];
    __shared__ __align__(16) float y0s[2][256];

    int tid = threadIdx.x;
    int j = tid >> 1, kh = tid & 1;
    int b0 = blockIdx.x * 2;
    int bb = tid >> 7, k = tid & 127;      // staging role (coalesced y0 loads)

    ull w1p[32], w2p[32];
    int wbase = j * 64 + kh * 32;
    const ull* W1 = (const ull*)Wih1;
    const ull* W2 = (const ull*)Whh1;
#pragma unroll
    for (int i = 0; i < 32; i++) { w1p[i] = W1[wbase + i]; w2p[i] = W2[wbase + i]; }

    if (tid < 128) bias_s[tid] = bih1[tid] + bhh1[tid];
    h1s[0][tid] = 0.0f;
    y0s[0][bb * 128 + k] = g_y0[((size_t)(b0 + bb) * T_ + 0) * H_ + k];
    float pf = g_y0[((size_t)(b0 + bb) * T_ + 1) * H_ + k];
    __syncthreads();

    for (int t = 0; t < T_; t++) {
        const ulonglong2* h2 = (const ulonglong2*)h1s[t & 1];
        const ulonglong2* y2 = (const ulonglong2*)y0s[t & 1];
        int hb = kh * 16;
        ull aY0 = 0, aY0b = 0, aH0 = 0, aH0b = 0;
        ull aY1 = 0, aY1b = 0, aH1 = 0, aH1b = 0;
#pragma unroll
        for (int i = 0; i < 16; i++) {
            ulonglong2 yv0 = y2[hb + i];
            ulonglong2 yv1 = y2[32 + hb + i];
            ulonglong2 hv0 = h2[hb + i];
            ulonglong2 hv1 = h2[32 + hb + i];
            aY0  = ffma2(w1p[2 * i],     yv0.x, aY0);
            aY0b = ffma2(w1p[2 * i + 1], yv0.y, aY0b);
            aH0  = ffma2(w2p[2 * i],     hv0.x, aH0);
            aH0b = ffma2(w2p[2 * i + 1], hv0.y, aH0b);
            aY1  = ffma2(w1p[2 * i],     yv1.x, aY1);
            aY1b = ffma2(w1p[2 * i + 1], yv1.y, aY1b);
            aH1  = ffma2(w2p[2 * i],     hv1.x, aH1);
            aH1b = ffma2(w2p[2 * i + 1], hv1.y, aH1b);
        }
        float p0 = hadd(aY0) + hadd(aY0b) + hadd(aH0) + hadd(aH0b);
        float p1 = hadd(aY1) + hadd(aY1b) + hadd(aH1) + hadd(aH1b);
        p0 += __shfl_xor_sync(0xffffffffu, p0, 1);
        p1 += __shfl_xor_sync(0xffffffffu, p1, 1);

        float v = kh ? p1 : p0;
        float nh = tanhf(v + bias_s[j]);
        h1s[(t + 1) & 1][kh * 128 + j] = nh;
        g_y1[((size_t)(b0 + kh) * T_ + t) * H_ + j] = nh;
        if (t == T_ - 1) hid1[(b0 + kh) * H_ + j] = nh;

        // stage y0(t+1) from prefetch reg, issue prefetch for t+2
        y0s[(t + 1) & 1][bb * 128 + k] = pf;
        int tn = (t + 2 < T_) ? (t + 2) : (T_ - 1);
        pf = g_y0[((size_t)(b0 + bb) * T_ + tn) * H_ + k];
        __syncthreads();
    }
}

// ---------------------------------------------------------------------------
// FC GEMM: out[r][v] = sum_h y1[r][h]*fc_W[v][h] + fc_b[v]
// Tile 64 rows x 96 cols / CTA; W (transposed) staged in 48KB smem; y1 read
// via L1 (broadcast across lanes). 4x6 accs/thread -> ~90 regs -> 2 CTAs/SM.
// ---------------------------------------------------------------------------
__global__ void __launch_bounds__(256, 2)
k_fc(const float* __restrict__ fcb, float* __restrict__ out) {
    extern __shared__ float smw[];         // [kp=64][v=96] float2 = 48KB
    int tid = threadIdx.x;
    for (int i = tid; i < 64 * 96 * 2 / 4; i += 256)
        ((float4*)smw)[i] = ((const float4*)g_fcWt)[i];
    __syncthreads();

    int tx = tid & 15, ty = tid >> 4;
    int row0 = blockIdx.x * 64 + ty * 4;
    const ull* yu = (const ull*)g_y1 + (size_t)row0 * 64;
    const ull* wsu = (const ull*)smw;
    int v0 = tx * 6;

    ull acc[4][6];
#pragma unroll
    for (int ii = 0; ii < 4; ii++)
#pragma unroll
        for (int jj = 0; jj < 6; jj++) acc[ii][jj] = 0;

#pragma unroll 2
    for (int kp = 0; kp < 64; kp++) {
        ull yv[4], wv[6];
#pragma unroll
        for (int ii = 0; ii < 4; ii++) yv[ii] = __ldg(yu + ii * 64 + kp);
#pragma unroll
        for (int jj = 0; jj < 6; jj++) wv[jj] = wsu[kp * 96 + v0 + jj];
#pragma unroll
        for (int ii = 0; ii < 4; ii++)
#pragma unroll
            for (int jj = 0; jj < 6; jj++)
                acc[ii][jj] = ffma2(yv[ii], wv[jj], acc[ii][jj]);
    }

    float bias[6];
#pragma unroll
    for (int jj = 0; jj < 6; jj++) bias[jj] = fcb[v0 + jj];

#pragma unroll
    for (int ii = 0; ii < 4; ii++) {
        float r[6];
#pragma unroll
        for (int jj = 0; jj < 6; jj++) r[jj] = hadd(acc[ii][jj]) + bias[jj];
        float* op = out + (size_t)(row0 + ii) * V_ + v0;
        ((float2*)op)[0] = make_float2(r[0], r[1]);
        ((float2*)op)[1] = make_float2(r[2], r[3]);
        ((float2*)op)[2] = make_float2(r[4], r[5]);
    }
}

// ---------------------------------------------------------------------------
extern "C" void kernel_launch(void* const* d_in, const int* in_sizes, int n_in,
                              void* d_out, int out_size) {
    const int*   x    = (const int*)d_in[0];
    const float* emb  = (const float*)d_in[1];
    const float* Wih0 = (const float*)d_in[2];
    const float* Whh0 = (const float*)d_in[3];
    const float* bih0 = (const float*)d_in[4];
    const float* bhh0 = (const float*)d_in[5];
    const float* Wih1 = (const float*)d_in[6];
    const float* Whh1 = (const float*)d_in[7];
    const float* bih1 = (const float*)d_in[8];
    const float* bhh1 = (const float*)d_in[9];
    const float* fcW  = (const float*)d_in[10];
    const float* fcb  = (const float*)d_in[11];

    float* out = (float*)d_out;
    float* hid = out + (size_t)B_ * T_ * V_;   // hidden [2,B,H] after logits

    cudaFuncSetAttribute(k_l0, cudaFuncAttributeMaxDynamicSharedMemorySize, 59392);
    cudaFuncSetAttribute(k_fc, cudaFuncAttributeMaxDynamicSharedMemorySize, 49152);

    k_proj<<<V_, H_>>>(emb, Wih0, bih0, bhh0);
    k_wt<<<24, 256>>>(fcW);
    k_l0<<<B_ / 2, 256, 59392>>>(x, Whh0, hid);
    k_l1<<<B_ / 2, 256>>>(Wih1, Whh1, bih1, bhh1, hid + B_ * H_);
    k_fc<<<(B_ * T_) / 64, 256, 49152>>>(fcb, out);
}